// round 9
// baseline (speedup 1.0000x reference)
#include <cuda_runtime.h>

// Problem constants (from reference)
#define NPTS   4096
#define BATCH  (1 << 20)
#define NNODE  4096
#define PLANE  (NNODE * NNODE)        // 16777216
#define TAU_MAX 10.0f

// LUTs: f_i(t) for t in [-1.0, 0.1] (x/dt MLP), g_i(t) for t in [0, 1] (y MLP).
// 4 basis values packed per point. (NPTS+1) points, ~64KB each -> L1 resident.
__device__ float4 g_tabX[NPTS + 1];
__device__ float4 g_tabY[NPTS + 1];

// softplus(100 z)/100, numerically stable, matches jax.nn.softplus to fp32.
__device__ __forceinline__ float sp100(float z) {
    float u = 100.0f * z;
    float r = fmaxf(u, 0.0f);
    float e = __expf(-fabsf(u));           // underflows to 0 for |u| large -> exact
    return (r + __logf(1.0f + e)) * 0.01f;
}

// Build both LUTs. One thread per (table, point); each computes all 4 bases.
__global__ void build_tables_kernel(
    const float* __restrict__ Wx1, const float* __restrict__ Wx2, const float* __restrict__ Wx3,
    const float* __restrict__ Wy1, const float* __restrict__ Wy2, const float* __restrict__ Wy3,
    const float* __restrict__ bx1, const float* __restrict__ bx2, const float* __restrict__ bx3,
    const float* __restrict__ by1, const float* __restrict__ by2, const float* __restrict__ by3)
{
    int tid = blockIdx.x * blockDim.x + threadIdx.x;
    if (tid >= 2 * (NPTS + 1)) return;
    bool isY = (tid >= (NPTS + 1));
    int  i   = isY ? tid - (NPTS + 1) : tid;
    float t  = isY ? (float)i * (1.0f / NPTS)
                   : (-1.0f + (float)i * (1.1f / NPTS));

    const float* W1 = isY ? Wy1 : Wx1;
    const float* W2 = isY ? Wy2 : Wx2;
    const float* W3 = isY ? Wy3 : Wx3;
    const float* b1 = isY ? by1 : bx1;
    const float* b2 = isY ? by2 : bx2;
    const float* b3 = isY ? by3 : bx3;

    float o[4];
#pragma unroll
    for (int n = 0; n < 4; n++) {
        float h1[5];
#pragma unroll
        for (int w = 0; w < 5; w++)
            h1[w] = sp100(fmaf(t, __ldg(&W1[n * 5 + w]), __ldg(&b1[n * 5 + w])));
        float h2[5];
#pragma unroll
        for (int v = 0; v < 5; v++) {
            float z = __ldg(&b2[n * 5 + v]);
#pragma unroll
            for (int w = 0; w < 5; w++)
                z = fmaf(h1[w], __ldg(&W2[n * 25 + w * 5 + v]), z);
            h2[v] = sp100(z);
        }
        float z = __ldg(&b3[n]);
#pragma unroll
        for (int w = 0; w < 5; w++)
            z = fmaf(h2[w], __ldg(&W3[n * 5 + w]), z);
        o[n] = z;
    }
    float4 r = make_float4(o[0], o[1], o[2], o[3]);
    if (isY) g_tabY[i] = r; else g_tabX[i] = r;
}

// Main kernel: 4 samples per thread.
// Phase 1 (branchless): vector-load x/y, LUT interp, 4x4 GEMV with W -> cj[s][j], offsets, masks.
// Phase 2: front-batched 16 predicated gathers from B (default caching -> L2 collision hits).
// Phase 3: reduce, one STG.128.
__global__ void __launch_bounds__(256)
eval_kernel(const float4* __restrict__ x4, const float4* __restrict__ y4,
            const float* __restrict__ B, const float* __restrict__ W,
            float4* __restrict__ out4)
{
    int t = blockIdx.x * blockDim.x + threadIdx.x;   // samples 4t .. 4t+3

    // x/y are float2 per sample; float4 = 2 samples.
    float4 xa = __ldcs(&x4[2 * t]);
    float4 xb = __ldcs(&x4[2 * t + 1]);
    float4 ya = __ldcs(&y4[2 * t]);
    float4 yb = __ldcs(&y4[2 * t + 1]);

    float txs[4] = {xa.x, xa.z, xb.x, xb.z};
    float xis[4] = {xa.y, xa.w, xb.y, xb.w};
    float tys[4] = {ya.x, ya.z, yb.x, yb.z};
    float yis[4] = {ya.y, ya.w, yb.y, yb.w};

    const float4* W4 = (const float4*)W;
    float4 w0 = __ldg(&W4[0]);
    float4 w1 = __ldg(&W4[1]);
    float4 w2 = __ldg(&W4[2]);
    float4 w3 = __ldg(&W4[3]);

    float cj[4][4];
    int   off[4];
    bool  msk[4];

#pragma unroll
    for (int s = 0; s < 4; s++) {
        float dt = txs[s] - tys[s];
        msk[s] = (dt <= TAU_MAX);

        // x-table: u = dt/100 in (-1, 0.1]; clamp handles unmasked lanes safely.
        float px = fmaf(dt, 0.01f, 1.0f) * ((float)NPTS / 1.1f);
        px = fminf(fmaxf(px, 0.0f), (float)NPTS);
        int   ix = min((int)px, NPTS - 1);
        float fx = px - (float)ix;
        float4 a0 = __ldg(&g_tabX[ix]);
        float4 a1 = __ldg(&g_tabX[ix + 1]);

        // y-table: v = ty/100 in [0, 1)
        float py = tys[s] * (0.01f * (float)NPTS);
        py = fminf(fmaxf(py, 0.0f), (float)NPTS);
        int   iy = min((int)py, NPTS - 1);
        float fy = py - (float)iy;
        float4 c0 = __ldg(&g_tabY[iy]);
        float4 c1 = __ldg(&g_tabY[iy + 1]);

        float k0 = fmaf(fx, a1.x - a0.x, a0.x) * fmaf(fy, c1.x - c0.x, c0.x);
        float k1 = fmaf(fx, a1.y - a0.y, a0.y) * fmaf(fy, c1.y - c0.y, c0.y);
        float k2 = fmaf(fx, a1.z - a0.z, a0.z) * fmaf(fy, c1.z - c0.z, c0.z);
        float k3 = fmaf(fx, a1.w - a0.w, a0.w) * fmaf(fy, c1.w - c0.w, c0.w);

        cj[s][0] = fmaf(k3, w3.x, fmaf(k2, w2.x, fmaf(k1, w1.x, k0 * w0.x)));
        cj[s][1] = fmaf(k3, w3.y, fmaf(k2, w2.y, fmaf(k1, w1.y, k0 * w0.y)));
        cj[s][2] = fmaf(k3, w3.z, fmaf(k2, w2.z, fmaf(k1, w1.z, k0 * w0.z)));
        cj[s][3] = fmaf(k3, w3.w, fmaf(k2, w2.w, fmaf(k1, w1.w, k0 * w0.w)));

        off[s] = (int)yis[s] * NNODE + (int)xis[s];
    }

    // Phase 2: 16 predicated gathers, front-batched for MLP.
    float v[4][4];
#pragma unroll
    for (int s = 0; s < 4; s++) {
        const float* Bp = B + off[s];
        v[s][0] = msk[s] ? Bp[0] : 0.0f;
        v[s][1] = msk[s] ? Bp[PLANE] : 0.0f;
        v[s][2] = msk[s] ? Bp[2 * PLANE] : 0.0f;
        v[s][3] = msk[s] ? Bp[3 * PLANE] : 0.0f;
    }

    // Phase 3: reduce and store.
    float res[4];
#pragma unroll
    for (int s = 0; s < 4; s++) {
        res[s] = fmaf(cj[s][3], v[s][3],
                 fmaf(cj[s][2], v[s][2],
                 fmaf(cj[s][1], v[s][1], cj[s][0] * v[s][0])));
        res[s] = msk[s] ? res[s] : 0.0f;
    }
    out4[t] = make_float4(res[0], res[1], res[2], res[3]);
}

extern "C" void kernel_launch(void* const* d_in, const int* in_sizes, int n_in,
                              void* d_out, int out_size)
{
    const float* x   = (const float*)d_in[0];
    const float* y   = (const float*)d_in[1];
    const float* B   = (const float*)d_in[2];
    const float* Wx1 = (const float*)d_in[3];
    const float* Wx2 = (const float*)d_in[4];
    const float* Wx3 = (const float*)d_in[5];
    const float* Wy1 = (const float*)d_in[6];
    const float* Wy2 = (const float*)d_in[7];
    const float* Wy3 = (const float*)d_in[8];
    const float* bx1 = (const float*)d_in[9];
    const float* bx2 = (const float*)d_in[10];
    const float* bx3 = (const float*)d_in[11];
    const float* by1 = (const float*)d_in[12];
    const float* by2 = (const float*)d_in[13];
    const float* by3 = (const float*)d_in[14];
    const float* W   = (const float*)d_in[15];

    int build_threads = 2 * (NPTS + 1);
    build_tables_kernel<<<(build_threads + 255) / 256, 256>>>(
        Wx1, Wx2, Wx3, Wy1, Wy2, Wy3, bx1, bx2, bx3, by1, by2, by3);

    eval_kernel<<<BATCH / (256 * 4), 256>>>(
        (const float4*)x, (const float4*)y, B, W, (float4*)d_out);
}

// round 10
// speedup vs baseline: 1.1224x; 1.1224x over previous
#include <cuda_runtime.h>

// Problem constants (from reference)
#define NPTS   4096
#define BATCH  (1 << 20)
#define NNODE  4096
#define PLANE  (NNODE * NNODE)        // 16777216
#define TAU_MAX 10.0f

// LUTs: f_i(t) for t in [-1.0, 0.1] (x/dt MLP), g_i(t) for t in [0, 1] (y MLP).
// 4 basis values packed per point. (NPTS+1) points, ~64KB each -> L1 resident.
__device__ float4 g_tabX[NPTS + 1];
__device__ float4 g_tabY[NPTS + 1];

// softplus(100 z)/100, numerically stable, matches jax.nn.softplus to fp32.
__device__ __forceinline__ float sp100(float z) {
    float u = 100.0f * z;
    float r = fmaxf(u, 0.0f);
    float e = __expf(-fabsf(u));           // underflows to 0 for |u| large -> exact
    return (r + __logf(1.0f + e)) * 0.01f;
}

// Build both LUTs. One thread per (table, point); each computes all 4 bases.
__global__ void build_tables_kernel(
    const float* __restrict__ Wx1, const float* __restrict__ Wx2, const float* __restrict__ Wx3,
    const float* __restrict__ Wy1, const float* __restrict__ Wy2, const float* __restrict__ Wy3,
    const float* __restrict__ bx1, const float* __restrict__ bx2, const float* __restrict__ bx3,
    const float* __restrict__ by1, const float* __restrict__ by2, const float* __restrict__ by3)
{
    int tid = blockIdx.x * blockDim.x + threadIdx.x;
    if (tid >= 2 * (NPTS + 1)) return;
    bool isY = (tid >= (NPTS + 1));
    int  i   = isY ? tid - (NPTS + 1) : tid;
    float t  = isY ? (float)i * (1.0f / NPTS)
                   : (-1.0f + (float)i * (1.1f / NPTS));

    const float* W1 = isY ? Wy1 : Wx1;
    const float* W2 = isY ? Wy2 : Wx2;
    const float* W3 = isY ? Wy3 : Wx3;
    const float* b1 = isY ? by1 : bx1;
    const float* b2 = isY ? by2 : bx2;
    const float* b3 = isY ? by3 : bx3;

    float o[4];
#pragma unroll
    for (int n = 0; n < 4; n++) {
        float h1[5];
#pragma unroll
        for (int w = 0; w < 5; w++)
            h1[w] = sp100(fmaf(t, __ldg(&W1[n * 5 + w]), __ldg(&b1[n * 5 + w])));
        float h2[5];
#pragma unroll
        for (int v = 0; v < 5; v++) {
            float z = __ldg(&b2[n * 5 + v]);
#pragma unroll
            for (int w = 0; w < 5; w++)
                z = fmaf(h1[w], __ldg(&W2[n * 25 + w * 5 + v]), z);
            h2[v] = sp100(z);
        }
        float z = __ldg(&b3[n]);
#pragma unroll
        for (int w = 0; w < 5; w++)
            z = fmaf(h2[w], __ldg(&W3[n * 5 + w]), z);
        o[n] = z;
    }
    float4 r = make_float4(o[0], o[1], o[2], o[3]);
    if (isY) g_tabY[i] = r; else g_tabX[i] = r;
}

// Main kernel: 1 sample/thread (high occupancy), gather-first issue order.
//   1. load x,y
//   2. mask + offset -> issue 4 predicated B gathers immediately (longest latency first)
//   3. overlap: L1 table interp + 4x4 GEMV with W while gathers are in flight
//   4. reduce, select, store
__global__ void __launch_bounds__(256)
eval_kernel(const float2* __restrict__ x, const float2* __restrict__ y,
            const float* __restrict__ B, const float* __restrict__ W,
            float* __restrict__ out)
{
    int b = blockIdx.x * blockDim.x + threadIdx.x;

    float2 xv = __ldcs(&x[b]);   // (tx, xi_as_float)
    float2 yv = __ldcs(&y[b]);   // (ty, yi_as_float)
    float dt = xv.x - yv.x;
    bool  m  = (dt <= TAU_MAX);

    // ---- Phase 2: issue the long-latency gathers FIRST (predicated, no branch,
    // no extra traffic from unmasked lanes). ----
    int off = (int)yv.y * NNODE + (int)xv.y;
    const float* Bp = B + off;
    float v0 = m ? Bp[0]         : 0.0f;
    float v1 = m ? Bp[PLANE]     : 0.0f;
    float v2 = m ? Bp[2 * PLANE] : 0.0f;
    float v3 = m ? Bp[3 * PLANE] : 0.0f;

    // ---- Phase 3: table interp + GEMV while gathers are in flight. ----
    // x-table: u = dt/100 in (-1, 0.1]; clamp keeps unmasked lanes in range.
    float px = fmaf(dt, 0.01f, 1.0f) * ((float)NPTS / 1.1f);
    px = fminf(fmaxf(px, 0.0f), (float)NPTS);
    int   ix = min((int)px, NPTS - 1);
    float fx = px - (float)ix;
    float4 a0 = __ldg(&g_tabX[ix]);
    float4 a1 = __ldg(&g_tabX[ix + 1]);

    // y-table: v = ty/100 in [0, 1)
    float py = yv.x * (0.01f * (float)NPTS);
    py = fminf(fmaxf(py, 0.0f), (float)NPTS);
    int   iy = min((int)py, NPTS - 1);
    float fy = py - (float)iy;
    float4 c0 = __ldg(&g_tabY[iy]);
    float4 c1 = __ldg(&g_tabY[iy + 1]);

    float k0 = fmaf(fx, a1.x - a0.x, a0.x) * fmaf(fy, c1.x - c0.x, c0.x);
    float k1 = fmaf(fx, a1.y - a0.y, a0.y) * fmaf(fy, c1.y - c0.y, c0.y);
    float k2 = fmaf(fx, a1.z - a0.z, a0.z) * fmaf(fy, c1.z - c0.z, c0.z);
    float k3 = fmaf(fx, a1.w - a0.w, a0.w) * fmaf(fy, c1.w - c0.w, c0.w);

    // c_j = sum_i k_i * W[i][j];  W rows are float4 over j (L1/const hit)
    const float4* W4 = (const float4*)W;
    float4 w0 = __ldg(&W4[0]);
    float4 w1 = __ldg(&W4[1]);
    float4 w2 = __ldg(&W4[2]);
    float4 w3 = __ldg(&W4[3]);
    float cj0 = fmaf(k3, w3.x, fmaf(k2, w2.x, fmaf(k1, w1.x, k0 * w0.x)));
    float cj1 = fmaf(k3, w3.y, fmaf(k2, w2.y, fmaf(k1, w1.y, k0 * w0.y)));
    float cj2 = fmaf(k3, w3.z, fmaf(k2, w2.z, fmaf(k1, w1.z, k0 * w0.z)));
    float cj3 = fmaf(k3, w3.w, fmaf(k2, w2.w, fmaf(k1, w1.w, k0 * w0.w)));

    // ---- Phase 4: reduce (first consumption of gather results), select, store. ----
    float res = fmaf(cj3, v3, fmaf(cj2, v2, fmaf(cj1, v1, cj0 * v0)));
    out[b] = m ? res : 0.0f;
}

extern "C" void kernel_launch(void* const* d_in, const int* in_sizes, int n_in,
                              void* d_out, int out_size)
{
    const float* x   = (const float*)d_in[0];
    const float* y   = (const float*)d_in[1];
    const float* B   = (const float*)d_in[2];
    const float* Wx1 = (const float*)d_in[3];
    const float* Wx2 = (const float*)d_in[4];
    const float* Wx3 = (const float*)d_in[5];
    const float* Wy1 = (const float*)d_in[6];
    const float* Wy2 = (const float*)d_in[7];
    const float* Wy3 = (const float*)d_in[8];
    const float* bx1 = (const float*)d_in[9];
    const float* bx2 = (const float*)d_in[10];
    const float* bx3 = (const float*)d_in[11];
    const float* by1 = (const float*)d_in[12];
    const float* by2 = (const float*)d_in[13];
    const float* by3 = (const float*)d_in[14];
    const float* W   = (const float*)d_in[15];

    int build_threads = 2 * (NPTS + 1);
    build_tables_kernel<<<(build_threads + 255) / 256, 256>>>(
        Wx1, Wx2, Wx3, Wy1, Wy2, Wy3, bx1, bx2, bx3, by1, by2, by3);

    eval_kernel<<<BATCH / 256, 256>>>(
        (const float2*)x, (const float2*)y, B, W, (float*)d_out);
}

// round 11
// speedup vs baseline: 1.1778x; 1.0494x over previous
#include <cuda_runtime.h>

// Problem constants (from reference)
#define NPTS   4096
#define BATCH  (1 << 20)
#define NNODE  4096
#define PLANE  (NNODE * NNODE)        // 16777216
#define TAU_MAX 10.0f

// LUTs stored as flat float arrays, read as float4 per point in eval.
// f_i(t) for t in [-1.0, 0.1] (x/dt MLP), g_i(t) for t in [0, 1] (y MLP).
__device__ __align__(16) float g_tabX[(NPTS + 1) * 4];
__device__ __align__(16) float g_tabY[(NPTS + 1) * 4];

// softplus(100 z)/100, numerically stable, matches jax.nn.softplus to fp32.
__device__ __forceinline__ float sp100(float z) {
    float u = 100.0f * z;
    float r = fmaxf(u, 0.0f);
    float e = __expf(-fabsf(u));           // underflows to 0 for |u| large -> exact
    return (r + __logf(1.0f + e)) * 0.01f;
}

// Build both LUTs. One thread per (table, basis n, point): 2*4*(NPTS+1) threads,
// each evaluates ONE 1->5->5->1 MLP chain (20 sp100). Fires the PDL trigger
// immediately so the dependent eval kernel can start its independent phase.
__global__ void build_tables_kernel(
    const float* __restrict__ Wx1, const float* __restrict__ Wx2, const float* __restrict__ Wx3,
    const float* __restrict__ Wy1, const float* __restrict__ Wy2, const float* __restrict__ Wy3,
    const float* __restrict__ bx1, const float* __restrict__ bx2, const float* __restrict__ bx3,
    const float* __restrict__ by1, const float* __restrict__ by2, const float* __restrict__ by3)
{
#if __CUDA_ARCH__ >= 900
    cudaTriggerProgrammaticLaunchCompletion();
#endif
    int tid = blockIdx.x * blockDim.x + threadIdx.x;
    if (tid >= 8 * (NPTS + 1)) return;
    int  i   = tid & (NPTS);               // NPTS = 4096 = 2^12; i in [0, 4096]
    int  rem = tid >> 12;                  // careful: (NPTS+1) not power of 2 -> do it exactly
    // Exact decomposition (NPTS+1 = 4097):
    i   = tid % (NPTS + 1);
    rem = tid / (NPTS + 1);                // 0..7
    int  n   = rem & 3;                    // basis index
    bool isY = (rem >> 2) != 0;

    float t = isY ? (float)i * (1.0f / NPTS)
                  : (-1.0f + (float)i * (1.1f / NPTS));

    const float* W1 = isY ? Wy1 : Wx1;
    const float* W2 = isY ? Wy2 : Wx2;
    const float* W3 = isY ? Wy3 : Wx3;
    const float* b1 = isY ? by1 : bx1;
    const float* b2 = isY ? by2 : bx2;
    const float* b3 = isY ? by3 : bx3;

    float h1[5];
#pragma unroll
    for (int w = 0; w < 5; w++)
        h1[w] = sp100(fmaf(t, __ldg(&W1[n * 5 + w]), __ldg(&b1[n * 5 + w])));
    float h2[5];
#pragma unroll
    for (int v = 0; v < 5; v++) {
        float z = __ldg(&b2[n * 5 + v]);
#pragma unroll
        for (int w = 0; w < 5; w++)
            z = fmaf(h1[w], __ldg(&W2[n * 25 + w * 5 + v]), z);
        h2[v] = sp100(z);
    }
    float z = __ldg(&b3[n]);
#pragma unroll
    for (int w = 0; w < 5; w++)
        z = fmaf(h2[w], __ldg(&W3[n * 5 + w]), z);

    float* tab = isY ? g_tabY : g_tabX;
    tab[i * 4 + n] = z;
}

// Main kernel (PDL secondary): starts while build runs.
//   independent phase: load x/y, mask+offset, 4 predicated B gathers, W load
//   cudaGridDependencySynchronize()  -- wait for build grid
//   dependent phase: L1 table interp + 4x4 GEMV + reduce + store
__global__ void __launch_bounds__(256)
eval_kernel(const float2* __restrict__ x, const float2* __restrict__ y,
            const float* __restrict__ B, const float* __restrict__ W,
            float* __restrict__ out)
{
    int b = blockIdx.x * blockDim.x + threadIdx.x;

    float2 xv = __ldcs(&x[b]);   // (tx, xi_as_float)
    float2 yv = __ldcs(&y[b]);   // (ty, yi_as_float)
    float dt = xv.x - yv.x;
    bool  m  = (dt <= TAU_MAX);

    // ---- Long-latency gathers first (predicated, no branch). Independent of tables. ----
    int off = (int)yv.y * NNODE + (int)xv.y;
    const float* Bp = B + off;
    float v0 = m ? Bp[0]         : 0.0f;
    float v1 = m ? Bp[PLANE]     : 0.0f;
    float v2 = m ? Bp[2 * PLANE] : 0.0f;
    float v3 = m ? Bp[3 * PLANE] : 0.0f;

    // W load: also independent of tables.
    const float4* W4 = (const float4*)W;
    float4 w0 = __ldg(&W4[0]);
    float4 w1 = __ldg(&W4[1]);
    float4 w2 = __ldg(&W4[2]);
    float4 w3 = __ldg(&W4[3]);

    // Table indices (pure arithmetic, independent).
    float px = fmaf(dt, 0.01f, 1.0f) * ((float)NPTS / 1.1f);
    px = fminf(fmaxf(px, 0.0f), (float)NPTS);
    int   ix = min((int)px, NPTS - 1);
    float fx = px - (float)ix;

    float py = yv.x * (0.01f * (float)NPTS);
    py = fminf(fmaxf(py, 0.0f), (float)NPTS);
    int   iy = min((int)py, NPTS - 1);
    float fy = py - (float)iy;

#if __CUDA_ARCH__ >= 900
    cudaGridDependencySynchronize();   // build tables now guaranteed visible
#endif

    const float4* tX = (const float4*)g_tabX;
    const float4* tY = (const float4*)g_tabY;
    float4 a0 = __ldg(&tX[ix]);
    float4 a1 = __ldg(&tX[ix + 1]);
    float4 c0 = __ldg(&tY[iy]);
    float4 c1 = __ldg(&tY[iy + 1]);

    float k0 = fmaf(fx, a1.x - a0.x, a0.x) * fmaf(fy, c1.x - c0.x, c0.x);
    float k1 = fmaf(fx, a1.y - a0.y, a0.y) * fmaf(fy, c1.y - c0.y, c0.y);
    float k2 = fmaf(fx, a1.z - a0.z, a0.z) * fmaf(fy, c1.z - c0.z, c0.z);
    float k3 = fmaf(fx, a1.w - a0.w, a0.w) * fmaf(fy, c1.w - c0.w, c0.w);

    float cj0 = fmaf(k3, w3.x, fmaf(k2, w2.x, fmaf(k1, w1.x, k0 * w0.x)));
    float cj1 = fmaf(k3, w3.y, fmaf(k2, w2.y, fmaf(k1, w1.y, k0 * w0.y)));
    float cj2 = fmaf(k3, w3.z, fmaf(k2, w2.z, fmaf(k1, w1.z, k0 * w0.z)));
    float cj3 = fmaf(k3, w3.w, fmaf(k2, w2.w, fmaf(k1, w1.w, k0 * w0.w)));

    float res = fmaf(cj3, v3, fmaf(cj2, v2, fmaf(cj1, v1, cj0 * v0)));
    out[b] = m ? res : 0.0f;
}

extern "C" void kernel_launch(void* const* d_in, const int* in_sizes, int n_in,
                              void* d_out, int out_size)
{
    const float* x   = (const float*)d_in[0];
    const float* y   = (const float*)d_in[1];
    const float* B   = (const float*)d_in[2];
    const float* Wx1 = (const float*)d_in[3];
    const float* Wx2 = (const float*)d_in[4];
    const float* Wx3 = (const float*)d_in[5];
    const float* Wy1 = (const float*)d_in[6];
    const float* Wy2 = (const float*)d_in[7];
    const float* Wy3 = (const float*)d_in[8];
    const float* bx1 = (const float*)d_in[9];
    const float* bx2 = (const float*)d_in[10];
    const float* bx3 = (const float*)d_in[11];
    const float* by1 = (const float*)d_in[12];
    const float* by2 = (const float*)d_in[13];
    const float* by3 = (const float*)d_in[14];
    const float* W   = (const float*)d_in[15];

    // Primary: build tables (fires PDL trigger at entry).
    int build_threads = 8 * (NPTS + 1);
    build_tables_kernel<<<(build_threads + 255) / 256, 256>>>(
        Wx1, Wx2, Wx3, Wy1, Wy2, Wy3, bx1, bx2, bx3, by1, by2, by3);

    // Secondary: eval, launched with programmatic stream serialization so its
    // independent phase overlaps the build kernel.
    cudaLaunchConfig_t cfg = {};
    cfg.gridDim  = dim3(BATCH / 256);
    cfg.blockDim = dim3(256);
    cfg.dynamicSmemBytes = 0;
    cfg.stream = 0;
    cudaLaunchAttribute attr[1];
    attr[0].id = cudaLaunchAttributeProgrammaticStreamSerialization;
    attr[0].val.programmaticStreamSerializationAllowed = 1;
    cfg.attrs = attr;
    cfg.numAttrs = 1;

    const float2* x2 = (const float2*)x;
    const float2* y2 = (const float2*)y;
    float* outp = (float*)d_out;
    cudaLaunchKernelEx(&cfg, eval_kernel, x2, y2, B, W, outp);
}

// round 12
// speedup vs baseline: 1.1858x; 1.0068x over previous
#include <cuda_runtime.h>

// Problem constants (from reference)
#define NPTS   4096
#define BATCH  (1 << 20)
#define NNODE  4096
#define PLANE  (NNODE * NNODE)        // 16777216
#define TAU_MAX 10.0f

// LUTs stored as flat float arrays, read as float4 per point in eval.
// f_i(t) for t in [-1.0, 0.1] (x/dt MLP), g_i(t) for t in [0, 1] (y MLP).
__device__ __align__(16) float g_tabX[(NPTS + 1) * 4];
__device__ __align__(16) float g_tabY[(NPTS + 1) * 4];

// softplus(100 z)/100, numerically stable, matches jax.nn.softplus to fp32.
__device__ __forceinline__ float sp100(float z) {
    float u = 100.0f * z;
    float r = fmaxf(u, 0.0f);
    float e = __expf(-fabsf(u));           // underflows to 0 for |u| large -> exact
    return (r + __logf(1.0f + e)) * 0.01f;
}

// Build both LUTs. One thread per (table, basis n, point): 2*4*(NPTS+1) threads,
// each evaluates ONE 1->5->5->1 MLP chain (20 sp100). Fires the PDL trigger
// immediately so the dependent eval kernel can start its independent phase.
__global__ void build_tables_kernel(
    const float* __restrict__ Wx1, const float* __restrict__ Wx2, const float* __restrict__ Wx3,
    const float* __restrict__ Wy1, const float* __restrict__ Wy2, const float* __restrict__ Wy3,
    const float* __restrict__ bx1, const float* __restrict__ bx2, const float* __restrict__ bx3,
    const float* __restrict__ by1, const float* __restrict__ by2, const float* __restrict__ by3)
{
#if __CUDA_ARCH__ >= 900
    cudaTriggerProgrammaticLaunchCompletion();
#endif
    int tid = blockIdx.x * blockDim.x + threadIdx.x;
    if (tid >= 8 * (NPTS + 1)) return;
    int  i   = tid % (NPTS + 1);
    int  rem = tid / (NPTS + 1);           // 0..7
    int  n   = rem & 3;                    // basis index
    bool isY = (rem >> 2) != 0;

    float t = isY ? (float)i * (1.0f / NPTS)
                  : (-1.0f + (float)i * (1.1f / NPTS));

    const float* W1 = isY ? Wy1 : Wx1;
    const float* W2 = isY ? Wy2 : Wx2;
    const float* W3 = isY ? Wy3 : Wx3;
    const float* b1 = isY ? by1 : bx1;
    const float* b2 = isY ? by2 : bx2;
    const float* b3 = isY ? by3 : bx3;

    float h1[5];
#pragma unroll
    for (int w = 0; w < 5; w++)
        h1[w] = sp100(fmaf(t, __ldg(&W1[n * 5 + w]), __ldg(&b1[n * 5 + w])));
    float h2[5];
#pragma unroll
    for (int v = 0; v < 5; v++) {
        float z = __ldg(&b2[n * 5 + v]);
#pragma unroll
        for (int w = 0; w < 5; w++)
            z = fmaf(h1[w], __ldg(&W2[n * 25 + w * 5 + v]), z);
        h2[v] = sp100(z);
    }
    float z = __ldg(&b3[n]);
#pragma unroll
    for (int w = 0; w < 5; w++)
        z = fmaf(h2[w], __ldg(&W3[n * 5 + w]), z);

    float* tab = isY ? g_tabY : g_tabX;
    tab[i * 4 + n] = z;
}

// Main kernel (PDL secondary): starts while build runs.
//   independent phase: load x/y, mask+offset, 4 predicated B gathers (L1-bypass),
//                      W load, table index arithmetic
//   cudaGridDependencySynchronize()  -- wait for build grid
//   dependent phase: L1-resident table interp + 4x4 GEMV + reduce + store
__global__ void __launch_bounds__(256)
eval_kernel(const float2* __restrict__ x, const float2* __restrict__ y,
            const float* __restrict__ B, const float* __restrict__ W,
            float* __restrict__ out)
{
    int b = blockIdx.x * blockDim.x + threadIdx.x;

    float2 xv = __ldcs(&x[b]);   // (tx, xi_as_float)
    float2 yv = __ldcs(&y[b]);   // (ty, yi_as_float)
    float dt = xv.x - yv.x;
    bool  m  = (dt <= TAU_MAX);

    // ---- Long-latency gathers first (predicated, no branch).
    // __ldcg: bypass L1 (protect the L1-resident LUTs), allocate in L2
    // (keep birthday-collision hits). ----
    int off = (int)yv.y * NNODE + (int)xv.y;
    const float* Bp = B + off;
    float v0 = m ? __ldcg(Bp)             : 0.0f;
    float v1 = m ? __ldcg(Bp + PLANE)     : 0.0f;
    float v2 = m ? __ldcg(Bp + 2 * PLANE) : 0.0f;
    float v3 = m ? __ldcg(Bp + 3 * PLANE) : 0.0f;

    // W load: independent of tables, tiny and hot in L1.
    const float4* W4 = (const float4*)W;
    float4 w0 = __ldg(&W4[0]);
    float4 w1 = __ldg(&W4[1]);
    float4 w2 = __ldg(&W4[2]);
    float4 w3 = __ldg(&W4[3]);

    // Table indices (pure arithmetic, independent).
    float px = fmaf(dt, 0.01f, 1.0f) * ((float)NPTS / 1.1f);
    px = fminf(fmaxf(px, 0.0f), (float)NPTS);
    int   ix = min((int)px, NPTS - 1);
    float fx = px - (float)ix;

    float py = yv.x * (0.01f * (float)NPTS);
    py = fminf(fmaxf(py, 0.0f), (float)NPTS);
    int   iy = min((int)py, NPTS - 1);
    float fy = py - (float)iy;

#if __CUDA_ARCH__ >= 900
    cudaGridDependencySynchronize();   // build tables now guaranteed visible
#endif

    const float4* tX = (const float4*)g_tabX;
    const float4* tY = (const float4*)g_tabY;
    float4 a0 = __ldg(&tX[ix]);
    float4 a1 = __ldg(&tX[ix + 1]);
    float4 c0 = __ldg(&tY[iy]);
    float4 c1 = __ldg(&tY[iy + 1]);

    float k0 = fmaf(fx, a1.x - a0.x, a0.x) * fmaf(fy, c1.x - c0.x, c0.x);
    float k1 = fmaf(fx, a1.y - a0.y, a0.y) * fmaf(fy, c1.y - c0.y, c0.y);
    float k2 = fmaf(fx, a1.z - a0.z, a0.z) * fmaf(fy, c1.z - c0.z, c0.z);
    float k3 = fmaf(fx, a1.w - a0.w, a0.w) * fmaf(fy, c1.w - c0.w, c0.w);

    float cj0 = fmaf(k3, w3.x, fmaf(k2, w2.x, fmaf(k1, w1.x, k0 * w0.x)));
    float cj1 = fmaf(k3, w3.y, fmaf(k2, w2.y, fmaf(k1, w1.y, k0 * w0.y)));
    float cj2 = fmaf(k3, w3.z, fmaf(k2, w2.z, fmaf(k1, w1.z, k0 * w0.z)));
    float cj3 = fmaf(k3, w3.w, fmaf(k2, w2.w, fmaf(k1, w1.w, k0 * w0.w)));

    float res = fmaf(cj3, v3, fmaf(cj2, v2, fmaf(cj1, v1, cj0 * v0)));
    __stcs(&out[b], m ? res : 0.0f);   // streaming store, no L1/L2 dwell needed
}

extern "C" void kernel_launch(void* const* d_in, const int* in_sizes, int n_in,
                              void* d_out, int out_size)
{
    const float* x   = (const float*)d_in[0];
    const float* y   = (const float*)d_in[1];
    const float* B   = (const float*)d_in[2];
    const float* Wx1 = (const float*)d_in[3];
    const float* Wx2 = (const float*)d_in[4];
    const float* Wx3 = (const float*)d_in[5];
    const float* Wy1 = (const float*)d_in[6];
    const float* Wy2 = (const float*)d_in[7];
    const float* Wy3 = (const float*)d_in[8];
    const float* bx1 = (const float*)d_in[9];
    const float* bx2 = (const float*)d_in[10];
    const float* bx3 = (const float*)d_in[11];
    const float* by1 = (const float*)d_in[12];
    const float* by2 = (const float*)d_in[13];
    const float* by3 = (const float*)d_in[14];
    const float* W   = (const float*)d_in[15];

    // Max-L1 carveout for eval (no smem used): 228KB L1 comfortably holds both
    // 64KB LUTs plus streaming input lines. Idempotent host-side call.
    cudaFuncSetAttribute(eval_kernel,
                         cudaFuncAttributePreferredSharedMemoryCarveout,
                         cudaSharedmemCarveoutMaxL1);

    // Primary: build tables (fires PDL trigger at entry).
    int build_threads = 8 * (NPTS + 1);
    build_tables_kernel<<<(build_threads + 255) / 256, 256>>>(
        Wx1, Wx2, Wx3, Wy1, Wy2, Wy3, bx1, bx2, bx3, by1, by2, by3);

    // Secondary: eval, launched with programmatic stream serialization so its
    // independent phase overlaps the build kernel.
    cudaLaunchConfig_t cfg = {};
    cfg.gridDim  = dim3(BATCH / 256);
    cfg.blockDim = dim3(256);
    cfg.dynamicSmemBytes = 0;
    cfg.stream = 0;
    cudaLaunchAttribute attr[1];
    attr[0].id = cudaLaunchAttributeProgrammaticStreamSerialization;
    attr[0].val.programmaticStreamSerializationAllowed = 1;
    cfg.attrs = attr;
    cfg.numAttrs = 1;

    const float2* x2 = (const float2*)x;
    const float2* y2 = (const float2*)y;
    float* outp = (float*)d_out;
    cudaLaunchKernelEx(&cfg, eval_kernel, x2, y2, B, W, outp);
}